// round 3
// baseline (speedup 1.0000x reference)
#include <cuda_runtime.h>
#include <math.h>

// Problem constants
constexpr int NN   = 30000;      // nodes
constexpr int EE   = 240000;     // edges (before self loops)
constexpr int GG   = 1000;       // graphs
constexpr int FF   = 78;         // in features
constexpr int HH   = 10;         // GAT heads
constexpr int HIDC = 780;        // F*H
constexpr int ET   = EE + NN;    // edges with self loops
constexpr int P1   = 1500;       // fc1 width
constexpr int PO   = 2 * HIDC;   // pooled width 1560
constexpr int OC   = 128;        // output classes

// ---- one big device scratch buffer (no allocations allowed) ----
constexpr size_t OFF_H    = 0;
constexpr size_t OFF_OUT1 = OFF_H    + (size_t)NN * HIDC;
constexpr size_t OFF_H2   = OFF_OUT1 + (size_t)NN * HIDC;
constexpr size_t OFF_OUT2 = OFF_H2   + (size_t)NN * HIDC;
constexpr size_t OFF_ASRC = OFF_OUT2 + (size_t)NN * HIDC;
constexpr size_t OFF_ADST = OFF_ASRC + (size_t)NN * HH;
constexpr size_t OFF_DINV = OFF_ADST + (size_t)NN * HH;
constexpr size_t OFF_POOL = OFF_DINV + NN;
constexpr size_t OFF_FC1  = OFF_POOL + (size_t)GG * PO;
constexpr size_t OFF_DEG  = OFF_FC1  + (size_t)GG * P1;
constexpr size_t OFF_ROWP = OFF_DEG  + NN;
constexpr size_t OFF_WPTR = OFF_ROWP + NN + 1;
constexpr size_t OFF_CSRC = OFF_WPTR + NN;
constexpr size_t OFF_CNT  = OFF_CSRC + ET;
constexpr size_t OFF_GST  = OFF_CNT  + GG;
constexpr size_t TOTALF   = OFF_GST  + GG + 1;

__device__ __align__(16) float g_buf[TOTALF];

// ============================================================
// Generic tiled SGEMM: C[M,Nc] = A[M,K] @ B[K,Nc] (+bias)(+relu)
// 128x128 block tile, BK=8, 8x8 per thread, 256 threads.
// ============================================================
template<bool BIAS, bool RELU>
__global__ __launch_bounds__(256)
void sgemm(const float* __restrict__ A, const float* __restrict__ B,
           const float* __restrict__ bias, float* __restrict__ C,
           int M, int K, int Nc)
{
    __shared__ float As[8][128];
    __shared__ float Bs[8][128];

    const int tid = threadIdx.x;
    const int m0 = blockIdx.y * 128;
    const int n0 = blockIdx.x * 128;

    const int a_row = tid >> 1;          // 0..127
    const int a_col = (tid & 1) * 4;     // 0 or 4
    const int b_row = tid >> 5;          // 0..7
    const int b_col = (tid & 31) * 4;    // 0..124

    const int ty = tid >> 4;             // 0..15
    const int tx = tid & 15;             // 0..15

    float acc[8][8];
#pragma unroll
    for (int i = 0; i < 8; i++)
#pragma unroll
        for (int j = 0; j < 8; j++) acc[i][j] = 0.f;

    for (int k0 = 0; k0 < K; k0 += 8) {
        // load A tile (guarded)
        float av[4];
        const int gm = m0 + a_row;
#pragma unroll
        for (int i = 0; i < 4; i++) {
            int gk = k0 + a_col + i;
            av[i] = (gm < M && gk < K) ? A[(size_t)gm * K + gk] : 0.f;
        }
#pragma unroll
        for (int i = 0; i < 4; i++) As[a_col + i][a_row] = av[i];

        // load B tile (guarded)
        float bv[4];
        const int gk = k0 + b_row;
#pragma unroll
        for (int i = 0; i < 4; i++) {
            int gn = n0 + b_col + i;
            bv[i] = (gk < K && gn < Nc) ? B[(size_t)gk * Nc + gn] : 0.f;
        }
        *(float4*)&Bs[b_row][b_col] = make_float4(bv[0], bv[1], bv[2], bv[3]);

        __syncthreads();

#pragma unroll
        for (int kk = 0; kk < 8; kk++) {
            float4 a0 = *(const float4*)&As[kk][ty * 8];
            float4 a1 = *(const float4*)&As[kk][ty * 8 + 4];
            float4 b0 = *(const float4*)&Bs[kk][tx * 8];
            float4 b1 = *(const float4*)&Bs[kk][tx * 8 + 4];
            float ar[8] = {a0.x, a0.y, a0.z, a0.w, a1.x, a1.y, a1.z, a1.w};
            float br[8] = {b0.x, b0.y, b0.z, b0.w, b1.x, b1.y, b1.z, b1.w};
#pragma unroll
            for (int i = 0; i < 8; i++)
#pragma unroll
                for (int j = 0; j < 8; j++)
                    acc[i][j] = fmaf(ar[i], br[j], acc[i][j]);
        }
        __syncthreads();
    }

#pragma unroll
    for (int i = 0; i < 8; i++) {
        int gm = m0 + ty * 8 + i;
        if (gm >= M) continue;
#pragma unroll
        for (int j = 0; j < 8; j++) {
            int gn = n0 + tx * 8 + j;
            if (gn >= Nc) continue;
            float v = acc[i][j];
            if (BIAS) v += bias[gn];
            if (RELU) v = v > 0.f ? v : 0.f;
            C[(size_t)gm * Nc + gn] = v;
        }
    }
}

// ============================================================
// Attention coefficients: a_src[n,h], a_dst[n,h] (warp per (n,h))
// ============================================================
__global__ void att_kernel(const float* __restrict__ h,
                           const float* __restrict__ att_s,
                           const float* __restrict__ att_d,
                           float* __restrict__ asrc, float* __restrict__ adst)
{
    int w = (blockIdx.x * blockDim.x + threadIdx.x) >> 5;
    if (w >= NN * HH) return;
    int lane = threadIdx.x & 31;
    int n = w / HH, hh = w % HH;
    const float* hp = h + (size_t)n * HIDC + hh * FF;
    const float* as = att_s + hh * FF;
    const float* ad = att_d + hh * FF;
    float s1 = 0.f, s2 = 0.f;
    for (int f = lane; f < FF; f += 32) {
        float v = hp[f];
        s1 += v * as[f];
        s2 += v * ad[f];
    }
#pragma unroll
    for (int o = 16; o; o >>= 1) {
        s1 += __shfl_down_sync(0xffffffffu, s1, o);
        s2 += __shfl_down_sync(0xffffffffu, s2, o);
    }
    if (!lane) { asrc[w] = s1; adst[w] = s2; }
}

// ============================================================
// Graph structure kernels
// ============================================================
__global__ void zero_int(int* p, int n)
{
    int i = blockIdx.x * blockDim.x + threadIdx.x;
    if (i < n) p[i] = 0;
}

__global__ void copy_int(const int* __restrict__ a, int* __restrict__ b, int n)
{
    int i = blockIdx.x * blockDim.x + threadIdx.x;
    if (i < n) b[i] = a[i];
}

__global__ void hist_deg(const int* __restrict__ ei, int* __restrict__ deg)
{
    int e = blockIdx.x * blockDim.x + threadIdx.x;
    if (e >= ET) return;
    int d = (e < EE) ? ei[EE + e] : (e - EE);
    atomicAdd(&deg[d], 1);
}

__global__ void hist_batch(const int* __restrict__ batch, int* __restrict__ cnt)
{
    int i = blockIdx.x * blockDim.x + threadIdx.x;
    if (i < NN) atomicAdd(&cnt[batch[i]], 1);
}

// single-block exclusive scan, out has n+1 entries (out[n] = total)
__global__ void scan_excl(const int* __restrict__ in, int* __restrict__ out, int n)
{
    __shared__ int sh[1024];
    __shared__ int carry;
    if (threadIdx.x == 0) carry = 0;
    __syncthreads();
    for (int base = 0; base < n; base += 1024) {
        int i = base + threadIdx.x;
        int v = (i < n) ? in[i] : 0;
        sh[threadIdx.x] = v;
        __syncthreads();
        for (int off = 1; off < 1024; off <<= 1) {
            int t = (threadIdx.x >= off) ? sh[threadIdx.x - off] : 0;
            __syncthreads();
            sh[threadIdx.x] += t;
            __syncthreads();
        }
        int c0 = carry;
        if (i < n) out[i] = c0 + sh[threadIdx.x] - v;
        __syncthreads();
        if (threadIdx.x == 0) carry = c0 + sh[1023];
        __syncthreads();
    }
    if (threadIdx.x == 0) out[n] = carry;
}

__global__ void scatter_csr(const int* __restrict__ ei, int* __restrict__ wptr,
                            int* __restrict__ csrc)
{
    int e = blockIdx.x * blockDim.x + threadIdx.x;
    if (e >= ET) return;
    int s = (e < EE) ? ei[e] : (e - EE);
    int d = (e < EE) ? ei[EE + e] : (e - EE);
    int pos = atomicAdd(&wptr[d], 1);
    csrc[pos] = s;
}

__global__ void dinv_kernel(const int* __restrict__ deg, float* __restrict__ dinv)
{
    int i = blockIdx.x * blockDim.x + threadIdx.x;
    if (i < NN) dinv[i] = rsqrtf(fmaxf((float)deg[i], 1.f));
}

// ============================================================
// GAT softmax-aggregate: warp per destination node.
// out1[d, :] = relu( sum_j alpha[j,h]*h[src_j, h*F+f] + b_gat )
// ============================================================
__global__ __launch_bounds__(256)
void gat_agg(const float* __restrict__ h, const float* __restrict__ asrc,
             const float* __restrict__ adst, const int* __restrict__ rowptr,
             const int* __restrict__ csrc, const float* __restrict__ bgat,
             float* __restrict__ out1)
{
    __shared__ float wsh[8][HH];
    int warp = (blockIdx.x * 256 + threadIdx.x) >> 5;
    if (warp >= NN) return;
    int lane = threadIdx.x & 31;
    float* myw = wsh[(threadIdx.x >> 5)];
    int d = warp;
    int jb = rowptr[d], je = rowptr[d + 1];

    float ad = (lane < HH) ? adst[d * HH + lane] : 0.f;

    // pass 1: softmax denominator per head (lanes 0..9)
    float denom = 0.f;
    for (int j = jb; j < je; j++) {
        int s = csrc[j];
        if (lane < HH) {
            float ev = asrc[s * HH + lane] + ad;
            ev = ev > 0.f ? ev : 0.2f * ev;
            denom += __expf(ev);
        }
    }

    // precompute head index for each of this lane's features
    int hd[25];
#pragma unroll
    for (int k = 0; k < 25; k++) {
        int t = lane + k * 32;
        hd[k] = (t < HIDC) ? (t / FF) : 0;
    }

    float acc[25];
#pragma unroll
    for (int k = 0; k < 25; k++) acc[k] = 0.f;

    // pass 2: weighted aggregate
    for (int j = jb; j < je; j++) {
        int s = csrc[j];
        if (lane < HH) {
            float ev = asrc[s * HH + lane] + ad;
            ev = ev > 0.f ? ev : 0.2f * ev;
            myw[lane] = __expf(ev) / denom;
        }
        __syncwarp();
        const float* hp = h + (size_t)s * HIDC;
#pragma unroll
        for (int k = 0; k < 25; k++) {
            int t = lane + k * 32;
            if (t < HIDC) acc[k] = fmaf(myw[hd[k]], hp[t], acc[k]);
        }
        __syncwarp();
    }

    float* op = out1 + (size_t)d * HIDC;
#pragma unroll
    for (int k = 0; k < 25; k++) {
        int t = lane + k * 32;
        if (t < HIDC) {
            float v = acc[k] + bgat[t];
            op[t] = v > 0.f ? v : 0.f;
        }
    }
}

// ============================================================
// GCN normalized aggregate: warp per destination node.
// ============================================================
__global__ __launch_bounds__(256)
void gcn_agg(const float* __restrict__ h2, const float* __restrict__ dinv,
             const int* __restrict__ rowptr, const int* __restrict__ csrc,
             const float* __restrict__ bgcn, float* __restrict__ out2)
{
    int warp = (blockIdx.x * 256 + threadIdx.x) >> 5;
    if (warp >= NN) return;
    int lane = threadIdx.x & 31;
    int d = warp;
    int jb = rowptr[d], je = rowptr[d + 1];
    float dd = dinv[d];

    float acc[25];
#pragma unroll
    for (int k = 0; k < 25; k++) acc[k] = 0.f;

    for (int j = jb; j < je; j++) {
        int s = csrc[j];
        float w = dinv[s] * dd;
        const float* hp = h2 + (size_t)s * HIDC;
#pragma unroll
        for (int k = 0; k < 25; k++) {
            int t = lane + k * 32;
            if (t < HIDC) acc[k] = fmaf(w, hp[t], acc[k]);
        }
    }

    float* op = out2 + (size_t)d * HIDC;
#pragma unroll
    for (int k = 0; k < 25; k++) {
        int t = lane + k * 32;
        if (t < HIDC) {
            float v = acc[k] + bgcn[t];
            op[t] = v > 0.f ? v : 0.f;
        }
    }
}

// ============================================================
// Global mean/max pool, block per graph (batch is sorted)
// ============================================================
__global__ __launch_bounds__(256)
void pool_kernel(const float* __restrict__ out2, const int* __restrict__ gstart,
                 float* __restrict__ pooled)
{
    int g = blockIdx.x;
    int t0 = threadIdx.x;
    int start = gstart[g];
    int cnt = gstart[g + 1] - start;

    float s[4], mx[4];
#pragma unroll
    for (int k = 0; k < 4; k++) { s[k] = 0.f; mx[k] = -INFINITY; }

    for (int i = 0; i < cnt; i++) {
        const float* p = out2 + (size_t)(start + i) * HIDC;
#pragma unroll
        for (int k = 0; k < 4; k++) {
            int t = t0 + k * 256;
            if (t < HIDC) {
                float v = p[t];
                s[k] += v;
                mx[k] = fmaxf(mx[k], v);
            }
        }
    }
    float inv = 1.f / fmaxf((float)cnt, 1.f);
#pragma unroll
    for (int k = 0; k < 4; k++) {
        int t = t0 + k * 256;
        if (t < HIDC) {
            pooled[(size_t)g * PO + t] = s[k] * inv;
            pooled[(size_t)g * PO + HIDC + t] = (cnt > 0) ? mx[k] : 0.f;
        }
    }
}

// ============================================================
// Launch
// ============================================================
extern "C" void kernel_launch(void* const* d_in, const int* in_sizes, int n_in,
                              void* d_out, int out_size)
{
    const float* x     = (const float*)d_in[0];
    const int*   ei    = (const int*)  d_in[1];
    const int*   batch = (const int*)  d_in[2];
    const float* Wgat  = (const float*)d_in[3];
    const float* att_s = (const float*)d_in[4];
    const float* att_d = (const float*)d_in[5];
    const float* bgat  = (const float*)d_in[6];
    const float* Wgcn  = (const float*)d_in[7];
    const float* bgcn  = (const float*)d_in[8];
    const float* W1    = (const float*)d_in[9];
    const float* b1    = (const float*)d_in[10];
    const float* W2    = (const float*)d_in[11];
    const float* b2    = (const float*)d_in[12];
    float* out = (float*)d_out;

    float* base = nullptr;
    cudaGetSymbolAddress((void**)&base, g_buf);

    float* ph     = base + OFF_H;
    float* pout1  = base + OFF_OUT1;
    float* ph2    = base + OFF_H2;
    float* pout2  = base + OFF_OUT2;
    float* pasrc  = base + OFF_ASRC;
    float* padst  = base + OFF_ADST;
    float* pdinv  = base + OFF_DINV;
    float* ppool  = base + OFF_POOL;
    float* pfc1   = base + OFF_FC1;
    int*   pdeg   = (int*)(base + OFF_DEG);
    int*   prowp  = (int*)(base + OFF_ROWP);
    int*   pwptr  = (int*)(base + OFF_WPTR);
    int*   pcsrc  = (int*)(base + OFF_CSRC);
    int*   pcnt   = (int*)(base + OFF_CNT);
    int*   pgst   = (int*)(base + OFF_GST);

    // 1. h = x @ W_gat   [N, 780]
    {
        dim3 grid((HIDC + 127) / 128, (NN + 127) / 128);
        sgemm<false, false><<<grid, 256>>>(x, Wgat, nullptr, ph, NN, FF, HIDC);
    }

    // 2. attention coefficients
    {
        int warps = NN * HH;
        int blocks = (warps * 32 + 255) / 256;
        att_kernel<<<blocks, 256>>>(ph, att_s, att_d, pasrc, padst);
    }

    // 3. CSR build (degree -> rowptr -> scatter) + dinv
    zero_int<<<(NN + 255) / 256, 256>>>(pdeg, NN);
    hist_deg<<<(ET + 255) / 256, 256>>>(ei, pdeg);
    scan_excl<<<1, 1024>>>(pdeg, prowp, NN);
    copy_int<<<(NN + 255) / 256, 256>>>(prowp, pwptr, NN);
    scatter_csr<<<(ET + 255) / 256, 256>>>(ei, pwptr, pcsrc);
    dinv_kernel<<<(NN + 255) / 256, 256>>>(pdeg, pdinv);

    // 4. GAT softmax-aggregate + bias + relu
    gat_agg<<<(NN * 32 + 255) / 256, 256>>>(ph, pasrc, padst, prowp, pcsrc, bgat, pout1);

    // 5. h2 = out1 @ W_gcn   [N, 780]
    {
        dim3 grid((HIDC + 127) / 128, (NN + 127) / 128);
        sgemm<false, false><<<grid, 256>>>(pout1, Wgcn, nullptr, ph2, NN, HIDC, HIDC);
    }

    // 6. GCN aggregate + bias + relu
    gcn_agg<<<(NN * 32 + 255) / 256, 256>>>(ph2, pdinv, prowp, pcsrc, bgcn, pout2);

    // 7. graph node ranges (batch is sorted)
    zero_int<<<(GG + 255) / 256, 256>>>(pcnt, GG);
    hist_batch<<<(NN + 255) / 256, 256>>>(batch, pcnt);
    scan_excl<<<1, 1024>>>(pcnt, pgst, GG);

    // 8. mean/max pooling
    pool_kernel<<<GG, 256>>>(pout2, pgst, ppool);

    // 9. fc1 = relu(pooled @ W1 + b1)
    {
        dim3 grid((P1 + 127) / 128, (GG + 127) / 128);
        sgemm<true, true><<<grid, 256>>>(ppool, W1, b1, pfc1, GG, PO, P1);
    }

    // 10. out = fc1 @ W2 + b2
    {
        dim3 grid((OC + 127) / 128, (GG + 127) / 128);
        sgemm<true, false><<<grid, 256>>>(pfc1, W2, b2, out, GG, P1, OC);
    }
}

// round 5
// speedup vs baseline: 1.4546x; 1.4546x over previous
#include <cuda_runtime.h>
#include <math.h>
#include <stdint.h>

// Problem constants
constexpr int NN   = 30000;      // nodes
constexpr int EE   = 240000;     // edges (before self loops)
constexpr int GG   = 1000;       // graphs
constexpr int FF   = 78;         // in features
constexpr int HH   = 10;         // GAT heads
constexpr int HIDC = 780;        // F*H
constexpr int ET   = EE + NN;    // edges with self loops
constexpr int P1   = 1500;       // fc1 width
constexpr int PO   = 2 * HIDC;   // pooled width 1560
constexpr int OC   = 128;        // output classes

// ---- one big device scratch buffer (no allocations allowed) ----
constexpr size_t OFF_H    = 0;
constexpr size_t OFF_OUT1 = OFF_H    + (size_t)NN * HIDC;
constexpr size_t OFF_H2   = OFF_OUT1 + (size_t)NN * HIDC;
constexpr size_t OFF_OUT2 = OFF_H2   + (size_t)NN * HIDC;
constexpr size_t OFF_ASRC = OFF_OUT2 + (size_t)NN * HIDC;
constexpr size_t OFF_ADST = OFF_ASRC + (size_t)NN * HH;
constexpr size_t OFF_DINV = OFF_ADST + (size_t)NN * HH;
constexpr size_t OFF_POOL = OFF_DINV + NN;
constexpr size_t OFF_FC1  = OFF_POOL + (size_t)GG * PO;
constexpr size_t OFF_DEG  = OFF_FC1  + (size_t)GG * P1;
constexpr size_t OFF_ROWP = OFF_DEG  + NN;
constexpr size_t OFF_WPTR = OFF_ROWP + NN + 1;
constexpr size_t OFF_CSRC = OFF_WPTR + NN;
constexpr size_t OFF_CNT  = OFF_CSRC + ET;
constexpr size_t OFF_GST  = OFF_CNT  + GG;
constexpr size_t TOTALF   = OFF_GST  + GG + 1;

__device__ __align__(16) float g_buf[TOTALF];

// ============================================================
// TF32 tensor-core GEMM: C[M,Nc] = A[M,K] @ B[K,Nc] (+bias)(+relu)
// 128x128 block tile, BK=16, 256 threads (8 warps, 2x4 warp grid),
// warp tile 64x32 from 4x4 m16n8k8 tf32 mma tiles.
// ============================================================
__device__ __forceinline__ uint32_t f2tf32(float v)
{
    uint32_t r;
    asm("cvt.rna.tf32.f32 %0, %1;" : "=r"(r) : "f"(v));
    return r;
}

__device__ __forceinline__ void mma_tf32(float c[4],
                                         const uint32_t a[4],
                                         const uint32_t b[2])
{
    asm volatile(
        "mma.sync.aligned.m16n8k8.row.col.f32.tf32.tf32.f32 "
        "{%0,%1,%2,%3}, {%4,%5,%6,%7}, {%8,%9}, {%0,%1,%2,%3};"
        : "+f"(c[0]), "+f"(c[1]), "+f"(c[2]), "+f"(c[3])
        : "r"(a[0]), "r"(a[1]), "r"(a[2]), "r"(a[3]),
          "r"(b[0]), "r"(b[1]));
}

template<bool BIAS, bool RELU>
__global__ __launch_bounds__(256, 2)
void tf32_gemm(const float* __restrict__ A, const float* __restrict__ B,
               const float* __restrict__ bias, float* __restrict__ C,
               int M, int K, int Nc)
{
    // As[m][k]: row pad 20 -> fragment loads conflict-free (20*gid+tg covers all banks)
    // Bs[k][n]: row pad 136 -> 8*tg+gid covers all banks
    __shared__ __align__(16) uint32_t As[128][20];
    __shared__ __align__(16) uint32_t Bs[16][136];

    const int tid  = threadIdx.x;
    const int warp = tid >> 5, lane = tid & 31;
    const int gid  = lane >> 2, tg = lane & 3;
    const int wr   = warp >> 2, wc = warp & 3;        // 2 x 4 warp grid
    const int m0   = blockIdx.y * 128, n0 = blockIdx.x * 128;

    // global->smem load assignments
    const int a_row = tid >> 1;            // 0..127
    const int a_c0  = (tid & 1) * 8;       // 0 or 8
    const int b_r   = tid >> 4;            // 0..15
    const int b_c0  = (tid & 15) * 8;      // 0..120

    float acc[4][4][4];
#pragma unroll
    for (int i = 0; i < 4; i++)
#pragma unroll
        for (int j = 0; j < 4; j++)
#pragma unroll
            for (int k = 0; k < 4; k++) acc[i][j][k] = 0.f;

    for (int k0 = 0; k0 < K; k0 += 16) {
        // ---- load A tile (128 x 16), store as As[m][k] (tf32-converted)
        {
            const int gm = m0 + a_row;
#pragma unroll
            for (int ch = 0; ch < 2; ch++) {
                int c = a_c0 + ch * 4;
                int gk = k0 + c;
                uint32_t t0, t1, t2, t3;
                if (gm < M && gk + 3 < K) {
                    float4 v = *(const float4*)(A + (size_t)gm * K + gk);
                    t0 = f2tf32(v.x); t1 = f2tf32(v.y);
                    t2 = f2tf32(v.z); t3 = f2tf32(v.w);
                } else {
                    float v0 = (gm < M && gk + 0 < K) ? A[(size_t)gm * K + gk + 0] : 0.f;
                    float v1 = (gm < M && gk + 1 < K) ? A[(size_t)gm * K + gk + 1] : 0.f;
                    float v2 = (gm < M && gk + 2 < K) ? A[(size_t)gm * K + gk + 2] : 0.f;
                    float v3 = (gm < M && gk + 3 < K) ? A[(size_t)gm * K + gk + 3] : 0.f;
                    t0 = f2tf32(v0); t1 = f2tf32(v1);
                    t2 = f2tf32(v2); t3 = f2tf32(v3);
                }
                *(uint4*)&As[a_row][c] = make_uint4(t0, t1, t2, t3);
            }
        }
        // ---- load B tile (16 x 128), store as Bs[k][n]
        {
            const int gk = k0 + b_r;
#pragma unroll
            for (int ch = 0; ch < 2; ch++) {
                int c = b_c0 + ch * 4;
                int gn = n0 + c;
                uint32_t t0, t1, t2, t3;
                if (gk < K && gn + 3 < Nc) {
                    float4 v = *(const float4*)(B + (size_t)gk * Nc + gn);
                    t0 = f2tf32(v.x); t1 = f2tf32(v.y);
                    t2 = f2tf32(v.z); t3 = f2tf32(v.w);
                } else {
                    float v0 = (gk < K && gn + 0 < Nc) ? B[(size_t)gk * Nc + gn + 0] : 0.f;
                    float v1 = (gk < K && gn + 1 < Nc) ? B[(size_t)gk * Nc + gn + 1] : 0.f;
                    float v2 = (gk < K && gn + 2 < Nc) ? B[(size_t)gk * Nc + gn + 2] : 0.f;
                    float v3 = (gk < K && gn + 3 < Nc) ? B[(size_t)gk * Nc + gn + 3] : 0.f;
                    t0 = f2tf32(v0); t1 = f2tf32(v1);
                    t2 = f2tf32(v2); t3 = f2tf32(v3);
                }
                *(uint4*)&Bs[b_r][c] = make_uint4(t0, t1, t2, t3);
            }
        }
        __syncthreads();

        // ---- compute: 2 k-steps of 8
#pragma unroll
        for (int ks = 0; ks < 16; ks += 8) {
            uint32_t af[4][4];
#pragma unroll
            for (int mt = 0; mt < 4; mt++) {
                int m = wr * 64 + mt * 16;
                af[mt][0] = As[m + gid    ][ks + tg    ];
                af[mt][1] = As[m + gid + 8][ks + tg    ];
                af[mt][2] = As[m + gid    ][ks + tg + 4];
                af[mt][3] = As[m + gid + 8][ks + tg + 4];
            }
            uint32_t bf[4][2];
#pragma unroll
            for (int nt = 0; nt < 4; nt++) {
                int n = wc * 32 + nt * 8 + gid;
                bf[nt][0] = Bs[ks + tg    ][n];
                bf[nt][1] = Bs[ks + tg + 4][n];
            }
#pragma unroll
            for (int mt = 0; mt < 4; mt++)
#pragma unroll
                for (int nt = 0; nt < 4; nt++)
                    mma_tf32(acc[mt][nt], af[mt], bf[nt]);
        }
        __syncthreads();
    }

    // ---- epilogue
#pragma unroll
    for (int mt = 0; mt < 4; mt++) {
        int rm = m0 + wr * 64 + mt * 16 + gid;
#pragma unroll
        for (int nt = 0; nt < 4; nt++) {
            int cn = n0 + wc * 32 + nt * 8 + 2 * tg;
#pragma unroll
            for (int half = 0; half < 2; half++) {
                int r = rm + half * 8;
                if (r >= M) continue;
                float v0 = acc[mt][nt][half * 2 + 0];
                float v1 = acc[mt][nt][half * 2 + 1];
                if (cn < Nc) {
                    float v = v0;
                    if (BIAS) v += bias[cn];
                    if (RELU) v = v > 0.f ? v : 0.f;
                    C[(size_t)r * Nc + cn] = v;
                }
                if (cn + 1 < Nc) {
                    float v = v1;
                    if (BIAS) v += bias[cn + 1];
                    if (RELU) v = v > 0.f ? v : 0.f;
                    C[(size_t)r * Nc + cn + 1] = v;
                }
            }
        }
    }
}

// ============================================================
// Generic tiled SGEMM (fp32): used where accuracy matters
// ============================================================
template<bool BIAS, bool RELU>
__global__ __launch_bounds__(256)
void sgemm(const float* __restrict__ A, const float* __restrict__ B,
           const float* __restrict__ bias, float* __restrict__ C,
           int M, int K, int Nc)
{
    __shared__ float As[8][128];
    __shared__ float Bs[8][128];

    const int tid = threadIdx.x;
    const int m0 = blockIdx.y * 128;
    const int n0 = blockIdx.x * 128;

    const int a_row = tid >> 1;
    const int a_col = (tid & 1) * 4;
    const int b_row = tid >> 5;
    const int b_col = (tid & 31) * 4;

    const int ty = tid >> 4;
    const int tx = tid & 15;

    float acc[8][8];
#pragma unroll
    for (int i = 0; i < 8; i++)
#pragma unroll
        for (int j = 0; j < 8; j++) acc[i][j] = 0.f;

    for (int k0 = 0; k0 < K; k0 += 8) {
        float av[4];
        const int gm = m0 + a_row;
#pragma unroll
        for (int i = 0; i < 4; i++) {
            int gk = k0 + a_col + i;
            av[i] = (gm < M && gk < K) ? A[(size_t)gm * K + gk] : 0.f;
        }
#pragma unroll
        for (int i = 0; i < 4; i++) As[a_col + i][a_row] = av[i];

        float bv[4];
        const int gk = k0 + b_row;
#pragma unroll
        for (int i = 0; i < 4; i++) {
            int gn = n0 + b_col + i;
            bv[i] = (gk < K && gn < Nc) ? B[(size_t)gk * Nc + gn] : 0.f;
        }
        *(float4*)&Bs[b_row][b_col] = make_float4(bv[0], bv[1], bv[2], bv[3]);

        __syncthreads();

#pragma unroll
        for (int kk = 0; kk < 8; kk++) {
            float4 a0 = *(const float4*)&As[kk][ty * 8];
            float4 a1 = *(const float4*)&As[kk][ty * 8 + 4];
            float4 b0 = *(const float4*)&Bs[kk][tx * 8];
            float4 b1 = *(const float4*)&Bs[kk][tx * 8 + 4];
            float ar[8] = {a0.x, a0.y, a0.z, a0.w, a1.x, a1.y, a1.z, a1.w};
            float br[8] = {b0.x, b0.y, b0.z, b0.w, b1.x, b1.y, b1.z, b1.w};
#pragma unroll
            for (int i = 0; i < 8; i++)
#pragma unroll
                for (int j = 0; j < 8; j++)
                    acc[i][j] = fmaf(ar[i], br[j], acc[i][j]);
        }
        __syncthreads();
    }

#pragma unroll
    for (int i = 0; i < 8; i++) {
        int gm = m0 + ty * 8 + i;
        if (gm >= M) continue;
#pragma unroll
        for (int j = 0; j < 8; j++) {
            int gn = n0 + tx * 8 + j;
            if (gn >= Nc) continue;
            float v = acc[i][j];
            if (BIAS) v += bias[gn];
            if (RELU) v = v > 0.f ? v : 0.f;
            C[(size_t)gm * Nc + gn] = v;
        }
    }
}

// ============================================================
// Attention coefficients: a_src[n,h], a_dst[n,h] (warp per (n,h))
// ============================================================
__global__ void att_kernel(const float* __restrict__ h,
                           const float* __restrict__ att_s,
                           const float* __restrict__ att_d,
                           float* __restrict__ asrc, float* __restrict__ adst)
{
    int w = (blockIdx.x * blockDim.x + threadIdx.x) >> 5;
    if (w >= NN * HH) return;
    int lane = threadIdx.x & 31;
    int n = w / HH, hh = w % HH;
    const float* hp = h + (size_t)n * HIDC + hh * FF;
    const float* as = att_s + hh * FF;
    const float* ad = att_d + hh * FF;
    float s1 = 0.f, s2 = 0.f;
    for (int f = lane; f < FF; f += 32) {
        float v = hp[f];
        s1 += v * as[f];
        s2 += v * ad[f];
    }
#pragma unroll
    for (int o = 16; o; o >>= 1) {
        s1 += __shfl_down_sync(0xffffffffu, s1, o);
        s2 += __shfl_down_sync(0xffffffffu, s2, o);
    }
    if (!lane) { asrc[w] = s1; adst[w] = s2; }
}

// ============================================================
// Graph structure kernels
// ============================================================
__global__ void zero_int(int* p, int n)
{
    int i = blockIdx.x * blockDim.x + threadIdx.x;
    if (i < n) p[i] = 0;
}

__global__ void copy_int(const int* __restrict__ a, int* __restrict__ b, int n)
{
    int i = blockIdx.x * blockDim.x + threadIdx.x;
    if (i < n) b[i] = a[i];
}

__global__ void hist_deg(const int* __restrict__ ei, int* __restrict__ deg)
{
    int e = blockIdx.x * blockDim.x + threadIdx.x;
    if (e >= ET) return;
    int d = (e < EE) ? ei[EE + e] : (e - EE);
    atomicAdd(&deg[d], 1);
}

__global__ void hist_batch(const int* __restrict__ batch, int* __restrict__ cnt)
{
    int i = blockIdx.x * blockDim.x + threadIdx.x;
    if (i < NN) atomicAdd(&cnt[batch[i]], 1);
}

// single-block exclusive scan, out has n+1 entries (out[n] = total)
__global__ void scan_excl(const int* __restrict__ in, int* __restrict__ out, int n)
{
    __shared__ int sh[1024];
    __shared__ int carry;
    if (threadIdx.x == 0) carry = 0;
    __syncthreads();
    for (int base = 0; base < n; base += 1024) {
        int i = base + threadIdx.x;
        int v = (i < n) ? in[i] : 0;
        sh[threadIdx.x] = v;
        __syncthreads();
        for (int off = 1; off < 1024; off <<= 1) {
            int t = (threadIdx.x >= off) ? sh[threadIdx.x - off] : 0;
            __syncthreads();
            sh[threadIdx.x] += t;
            __syncthreads();
        }
        int c0 = carry;
        if (i < n) out[i] = c0 + sh[threadIdx.x] - v;
        __syncthreads();
        if (threadIdx.x == 0) carry = c0 + sh[1023];
        __syncthreads();
    }
    if (threadIdx.x == 0) out[n] = carry;
}

__global__ void scatter_csr(const int* __restrict__ ei, int* __restrict__ wptr,
                            int* __restrict__ csrc)
{
    int e = blockIdx.x * blockDim.x + threadIdx.x;
    if (e >= ET) return;
    int s = (e < EE) ? ei[e] : (e - EE);
    int d = (e < EE) ? ei[EE + e] : (e - EE);
    int pos = atomicAdd(&wptr[d], 1);
    csrc[pos] = s;
}

__global__ void dinv_kernel(const int* __restrict__ deg, float* __restrict__ dinv)
{
    int i = blockIdx.x * blockDim.x + threadIdx.x;
    if (i < NN) dinv[i] = rsqrtf(fmaxf((float)deg[i], 1.f));
}

// ============================================================
// GAT softmax-aggregate: warp per destination node.
// ============================================================
__global__ __launch_bounds__(256)
void gat_agg(const float* __restrict__ h, const float* __restrict__ asrc,
             const float* __restrict__ adst, const int* __restrict__ rowptr,
             const int* __restrict__ csrc, const float* __restrict__ bgat,
             float* __restrict__ out1)
{
    __shared__ float wsh[8][HH];
    int warp = (blockIdx.x * 256 + threadIdx.x) >> 5;
    if (warp >= NN) return;
    int lane = threadIdx.x & 31;
    float* myw = wsh[(threadIdx.x >> 5)];
    int d = warp;
    int jb = rowptr[d], je = rowptr[d + 1];

    float ad = (lane < HH) ? adst[d * HH + lane] : 0.f;

    float denom = 0.f;
    for (int j = jb; j < je; j++) {
        int s = csrc[j];
        if (lane < HH) {
            float ev = asrc[s * HH + lane] + ad;
            ev = ev > 0.f ? ev : 0.2f * ev;
            denom += __expf(ev);
        }
    }

    int hd[25];
#pragma unroll
    for (int k = 0; k < 25; k++) {
        int t = lane + k * 32;
        hd[k] = (t < HIDC) ? (t / FF) : 0;
    }

    float acc[25];
#pragma unroll
    for (int k = 0; k < 25; k++) acc[k] = 0.f;

    for (int j = jb; j < je; j++) {
        int s = csrc[j];
        if (lane < HH) {
            float ev = asrc[s * HH + lane] + ad;
            ev = ev > 0.f ? ev : 0.2f * ev;
            myw[lane] = __expf(ev) / denom;
        }
        __syncwarp();
        const float* hp = h + (size_t)s * HIDC;
#pragma unroll
        for (int k = 0; k < 25; k++) {
            int t = lane + k * 32;
            if (t < HIDC) acc[k] = fmaf(myw[hd[k]], hp[t], acc[k]);
        }
        __syncwarp();
    }

    float* op = out1 + (size_t)d * HIDC;
#pragma unroll
    for (int k = 0; k < 25; k++) {
        int t = lane + k * 32;
        if (t < HIDC) {
            float v = acc[k] + bgat[t];
            op[t] = v > 0.f ? v : 0.f;
        }
    }
}

// ============================================================
// GCN normalized aggregate: warp per destination node.
// ============================================================
__global__ __launch_bounds__(256)
void gcn_agg(const float* __restrict__ h2, const float* __restrict__ dinv,
             const int* __restrict__ rowptr, const int* __restrict__ csrc,
             const float* __restrict__ bgcn, float* __restrict__ out2)
{
    int warp = (blockIdx.x * 256 + threadIdx.x) >> 5;
    if (warp >= NN) return;
    int lane = threadIdx.x & 31;
    int d = warp;
    int jb = rowptr[d], je = rowptr[d + 1];
    float dd = dinv[d];

    float acc[25];
#pragma unroll
    for (int k = 0; k < 25; k++) acc[k] = 0.f;

    for (int j = jb; j < je; j++) {
        int s = csrc[j];
        float w = dinv[s] * dd;
        const float* hp = h2 + (size_t)s * HIDC;
#pragma unroll
        for (int k = 0; k < 25; k++) {
            int t = lane + k * 32;
            if (t < HIDC) acc[k] = fmaf(w, hp[t], acc[k]);
        }
    }

    float* op = out2 + (size_t)d * HIDC;
#pragma unroll
    for (int k = 0; k < 25; k++) {
        int t = lane + k * 32;
        if (t < HIDC) {
            float v = acc[k] + bgcn[t];
            op[t] = v > 0.f ? v : 0.f;
        }
    }
}

// ============================================================
// Global mean/max pool, block per graph (batch is sorted)
// ============================================================
__global__ __launch_bounds__(256)
void pool_kernel(const float* __restrict__ out2, const int* __restrict__ gstart,
                 float* __restrict__ pooled)
{
    int g = blockIdx.x;
    int t0 = threadIdx.x;
    int start = gstart[g];
    int cnt = gstart[g + 1] - start;

    float s[4], mx[4];
#pragma unroll
    for (int k = 0; k < 4; k++) { s[k] = 0.f; mx[k] = -INFINITY; }

    for (int i = 0; i < cnt; i++) {
        const float* p = out2 + (size_t)(start + i) * HIDC;
#pragma unroll
        for (int k = 0; k < 4; k++) {
            int t = t0 + k * 256;
            if (t < HIDC) {
                float v = p[t];
                s[k] += v;
                mx[k] = fmaxf(mx[k], v);
            }
        }
    }
    float inv = 1.f / fmaxf((float)cnt, 1.f);
#pragma unroll
    for (int k = 0; k < 4; k++) {
        int t = t0 + k * 256;
        if (t < HIDC) {
            pooled[(size_t)g * PO + t] = s[k] * inv;
            pooled[(size_t)g * PO + HIDC + t] = (cnt > 0) ? mx[k] : 0.f;
        }
    }
}

// ============================================================
// Launch
// ============================================================
extern "C" void kernel_launch(void* const* d_in, const int* in_sizes, int n_in,
                              void* d_out, int out_size)
{
    const float* x     = (const float*)d_in[0];
    const int*   ei    = (const int*)  d_in[1];
    const int*   batch = (const int*)  d_in[2];
    const float* Wgat  = (const float*)d_in[3];
    const float* att_s = (const float*)d_in[4];
    const float* att_d = (const float*)d_in[5];
    const float* bgat  = (const float*)d_in[6];
    const float* Wgcn  = (const float*)d_in[7];
    const float* bgcn  = (const float*)d_in[8];
    const float* W1    = (const float*)d_in[9];
    const float* b1    = (const float*)d_in[10];
    const float* W2    = (const float*)d_in[11];
    const float* b2    = (const float*)d_in[12];
    float* out = (float*)d_out;

    float* base = nullptr;
    cudaGetSymbolAddress((void**)&base, g_buf);

    float* ph     = base + OFF_H;
    float* pout1  = base + OFF_OUT1;
    float* ph2    = base + OFF_H2;
    float* pout2  = base + OFF_OUT2;
    float* pasrc  = base + OFF_ASRC;
    float* padst  = base + OFF_ADST;
    float* pdinv  = base + OFF_DINV;
    float* ppool  = base + OFF_POOL;
    float* pfc1   = base + OFF_FC1;
    int*   pdeg   = (int*)(base + OFF_DEG);
    int*   prowp  = (int*)(base + OFF_ROWP);
    int*   pwptr  = (int*)(base + OFF_WPTR);
    int*   pcsrc  = (int*)(base + OFF_CSRC);
    int*   pcnt   = (int*)(base + OFF_CNT);
    int*   pgst   = (int*)(base + OFF_GST);

    // 1. h = x @ W_gat   [N, 780]  (fp32: feeds attention softmax)
    {
        dim3 grid((HIDC + 127) / 128, (NN + 127) / 128);
        sgemm<false, false><<<grid, 256>>>(x, Wgat, nullptr, ph, NN, FF, HIDC);
    }

    // 2. attention coefficients
    {
        int warps = NN * HH;
        int blocks = (warps * 32 + 255) / 256;
        att_kernel<<<blocks, 256>>>(ph, att_s, att_d, pasrc, padst);
    }

    // 3. CSR build + dinv
    zero_int<<<(NN + 255) / 256, 256>>>(pdeg, NN);
    hist_deg<<<(ET + 255) / 256, 256>>>(ei, pdeg);
    scan_excl<<<1, 1024>>>(pdeg, prowp, NN);
    copy_int<<<(NN + 255) / 256, 256>>>(prowp, pwptr, NN);
    scatter_csr<<<(ET + 255) / 256, 256>>>(ei, pwptr, pcsrc);
    dinv_kernel<<<(NN + 255) / 256, 256>>>(pdeg, pdinv);

    // 4. GAT softmax-aggregate + bias + relu
    gat_agg<<<(NN * 32 + 255) / 256, 256>>>(ph, pasrc, padst, prowp, pcsrc, bgat, pout1);

    // 5. h2 = out1 @ W_gcn   [N, 780]  (TF32 tensor cores — dominant GEMM)
    {
        dim3 grid((HIDC + 127) / 128, (NN + 127) / 128);
        tf32_gemm<false, false><<<grid, 256>>>(pout1, Wgcn, nullptr, ph2, NN, HIDC, HIDC);
    }

    // 6. GCN aggregate + bias + relu
    gcn_agg<<<(NN * 32 + 255) / 256, 256>>>(ph2, pdinv, prowp, pcsrc, bgcn, pout2);

    // 7. graph node ranges (batch is sorted)
    zero_int<<<(GG + 255) / 256, 256>>>(pcnt, GG);
    hist_batch<<<(NN + 255) / 256, 256>>>(batch, pcnt);
    scan_excl<<<1, 1024>>>(pcnt, pgst, GG);

    // 8. mean/max pooling
    pool_kernel<<<GG, 256>>>(pout2, pgst, ppool);

    // 9. fc1 = relu(pooled @ W1 + b1)   (TF32 tensor cores)
    {
        dim3 grid((P1 + 127) / 128, (GG + 127) / 128);
        tf32_gemm<true, true><<<grid, 256>>>(ppool, W1, b1, pfc1, GG, PO, P1);
    }

    // 10. out = fc1 @ W2 + b2  (fp32: final layer, small)
    {
        dim3 grid((OC + 127) / 128, (GG + 127) / 128);
        sgemm<true, false><<<grid, 256>>>(pfc1, W2, b2, out, GG, P1, OC);
    }
}

// round 6
// speedup vs baseline: 1.7987x; 1.2365x over previous
#include <cuda_runtime.h>
#include <math.h>
#include <stdint.h>

// Problem constants
constexpr int NN   = 30000;      // nodes
constexpr int EE   = 240000;     // edges (before self loops)
constexpr int GG   = 1000;       // graphs
constexpr int FF   = 78;         // in features
constexpr int HH   = 10;         // GAT heads
constexpr int HIDC = 780;        // F*H
constexpr int ET   = EE + NN;    // edges with self loops
constexpr int P1   = 1500;       // fc1 width
constexpr int PO   = 2 * HIDC;   // pooled width 1560
constexpr int OC   = 128;        // output classes
constexpr int H4   = HIDC / 4;   // 195 float4 per feature row

// ---- one big device scratch buffer (no allocations allowed) ----
constexpr size_t OFF_H    = 0;
constexpr size_t OFF_OUT1 = OFF_H    + (size_t)NN * HIDC;
constexpr size_t OFF_H2   = OFF_OUT1 + (size_t)NN * HIDC;
constexpr size_t OFF_OUT2 = OFF_H2   + (size_t)NN * HIDC;
constexpr size_t OFF_ASRC = OFF_OUT2 + (size_t)NN * HIDC;
constexpr size_t OFF_ADST = OFF_ASRC + (size_t)NN * HH;
constexpr size_t OFF_DINV = OFF_ADST + (size_t)NN * HH;
constexpr size_t OFF_POOL = OFF_DINV + NN;
constexpr size_t OFF_FC1  = OFF_POOL + (size_t)GG * PO;
constexpr size_t OFF_DEG  = OFF_FC1  + (size_t)GG * P1;
constexpr size_t OFF_ROWP = OFF_DEG  + NN;
constexpr size_t OFF_WPTR = OFF_ROWP + NN + 1;
constexpr size_t OFF_CSRC = OFF_WPTR + NN;
constexpr size_t OFF_CNT  = OFF_CSRC + ET;
constexpr size_t OFF_GST  = OFF_CNT  + GG;
constexpr size_t TOTALF   = OFF_GST  + GG + 1;

__device__ __align__(16) float g_buf[TOTALF];

// ============================================================
// helpers
// ============================================================
__device__ __forceinline__ uint32_t f2tf32(float v)
{
    uint32_t r;
    asm("cvt.rna.tf32.f32 %0, %1;" : "=r"(r) : "f"(v));
    return r;
}

__device__ __forceinline__ void mma_tf32(float c[4],
                                         const uint32_t a[4],
                                         const uint32_t b[2])
{
    asm volatile(
        "mma.sync.aligned.m16n8k8.row.col.f32.tf32.tf32.f32 "
        "{%0,%1,%2,%3}, {%4,%5,%6,%7}, {%8,%9}, {%0,%1,%2,%3};"
        : "+f"(c[0]), "+f"(c[1]), "+f"(c[2]), "+f"(c[3])
        : "r"(a[0]), "r"(a[1]), "r"(a[2]), "r"(a[3]),
          "r"(b[0]), "r"(b[1]));
}

__device__ __forceinline__ void cp_async16(void* smem_dst, const void* gsrc, int nbytes)
{
    uint32_t d = (uint32_t)__cvta_generic_to_shared(smem_dst);
    asm volatile("cp.async.cg.shared.global [%0], [%1], 16, %2;"
                 :: "r"(d), "l"(gsrc), "r"(nbytes));
}
__device__ __forceinline__ void cp_commit() { asm volatile("cp.async.commit_group;"); }
template<int N> __device__ __forceinline__ void cp_wait()
{ asm volatile("cp.async.wait_group %0;" :: "n"(N)); }

// ============================================================
// Pipelined TF32 GEMM: C[M,Nc] = A[M,K] @ B[K,Nc] (+bias)(+relu)
// 128x128 block tile, BK=16, double-buffered cp.async, 256 thr.
// REQUIRES: K % 4 == 0, Nc % 4 == 0, A/B rows 16B-aligned
// (row strides K*4 and Nc*4 multiples of 16 -> K,Nc % 4 == 0).
// ============================================================
template<bool BIAS, bool RELU>
__global__ __launch_bounds__(256, 2)
void tf32_gemm_pipe(const float* __restrict__ A, const float* __restrict__ B,
                    const float* __restrict__ bias, float* __restrict__ C,
                    int M, int K, int Nc)
{
    __shared__ __align__(16) float As[2][128][20];
    __shared__ __align__(16) float Bs[2][16][136];

    const int tid  = threadIdx.x;
    const int warp = tid >> 5, lane = tid & 31;
    const int gid  = lane >> 2, tg = lane & 3;
    const int wr   = warp >> 2, wc = warp & 3;        // 2 x 4 warp grid
    const int m0   = blockIdx.y * 128, n0 = blockIdx.x * 128;

    const int a_row = tid >> 1;            // 0..127
    const int a_c0  = (tid & 1) * 8;       // 0 or 8
    const int b_r   = tid >> 4;            // 0..15
    const int b_c0  = (tid & 15) * 8;      // 0..120

    const int gmA = m0 + a_row;
    const float* a_base = A + (size_t)(gmA < M ? gmA : M - 1) * K;
    const bool a_rowok = (gmA < M);

    float acc[4][4][4];
#pragma unroll
    for (int i = 0; i < 4; i++)
#pragma unroll
        for (int j = 0; j < 4; j++)
#pragma unroll
            for (int k = 0; k < 4; k++) acc[i][j][k] = 0.f;

    const int nk = (K + 15) / 16;

    // ---- tile loader (cp.async; chunks are full-or-zero)
    auto load_tile = [&](int buf, int k0) {
#pragma unroll
        for (int ch = 0; ch < 2; ch++) {
            int c = a_c0 + ch * 4;
            int gk = k0 + c;
            bool ok = a_rowok && (gk + 4 <= K);
            const float* src = a_base + (gk + 4 <= K ? gk : 0);
            cp_async16(&As[buf][a_row][c], src, ok ? 16 : 0);
        }
        int gkB = k0 + b_r;
        const float* b_base = B + (size_t)(gkB < K ? gkB : K - 1) * Nc;
#pragma unroll
        for (int ch = 0; ch < 2; ch++) {
            int c = b_c0 + ch * 4;
            int gn = n0 + c;
            bool ok = (gkB < K) && (gn + 4 <= Nc);
            const float* src = b_base + (gn + 4 <= Nc ? gn : 0);
            cp_async16(&Bs[buf][b_r][c], src, ok ? 16 : 0);
        }
    };

    load_tile(0, 0);
    cp_commit();

    for (int t = 0; t < nk; t++) {
        int buf = t & 1;
        if (t + 1 < nk) load_tile(buf ^ 1, (t + 1) * 16);
        cp_commit();            // one group per iteration (possibly empty)
        cp_wait<1>();           // current tile complete
        __syncthreads();

#pragma unroll
        for (int ks = 0; ks < 16; ks += 8) {
            uint32_t af[4][4];
#pragma unroll
            for (int mt = 0; mt < 4; mt++) {
                int m = wr * 64 + mt * 16;
                af[mt][0] = f2tf32(As[buf][m + gid    ][ks + tg    ]);
                af[mt][1] = f2tf32(As[buf][m + gid + 8][ks + tg    ]);
                af[mt][2] = f2tf32(As[buf][m + gid    ][ks + tg + 4]);
                af[mt][3] = f2tf32(As[buf][m + gid + 8][ks + tg + 4]);
            }
            uint32_t bf[4][2];
#pragma unroll
            for (int nt = 0; nt < 4; nt++) {
                int n = wc * 32 + nt * 8 + gid;
                bf[nt][0] = f2tf32(Bs[buf][ks + tg    ][n]);
                bf[nt][1] = f2tf32(Bs[buf][ks + tg + 4][n]);
            }
#pragma unroll
            for (int mt = 0; mt < 4; mt++)
#pragma unroll
                for (int nt = 0; nt < 4; nt++)
                    mma_tf32(acc[mt][nt], af[mt], bf[nt]);
        }
        __syncthreads();
    }

    // ---- epilogue
#pragma unroll
    for (int mt = 0; mt < 4; mt++) {
        int rm = m0 + wr * 64 + mt * 16 + gid;
#pragma unroll
        for (int nt = 0; nt < 4; nt++) {
            int cn = n0 + wc * 32 + nt * 8 + 2 * tg;
#pragma unroll
            for (int half = 0; half < 2; half++) {
                int r = rm + half * 8;
                if (r >= M) continue;
                float v0 = acc[mt][nt][half * 2 + 0];
                float v1 = acc[mt][nt][half * 2 + 1];
                if (cn < Nc) {
                    float v = v0;
                    if (BIAS) v += bias[cn];
                    if (RELU) v = v > 0.f ? v : 0.f;
                    C[(size_t)r * Nc + cn] = v;
                }
                if (cn + 1 < Nc) {
                    float v = v1;
                    if (BIAS) v += bias[cn + 1];
                    if (RELU) v = v > 0.f ? v : 0.f;
                    C[(size_t)r * Nc + cn + 1] = v;
                }
            }
        }
    }
}

// ============================================================
// Generic tiled SGEMM (fp32): GAT layer (feeds softmax) + MLP2
// ============================================================
template<bool BIAS, bool RELU>
__global__ __launch_bounds__(256)
void sgemm(const float* __restrict__ A, const float* __restrict__ B,
           const float* __restrict__ bias, float* __restrict__ C,
           int M, int K, int Nc)
{
    __shared__ float As[8][128];
    __shared__ float Bs[8][128];

    const int tid = threadIdx.x;
    const int m0 = blockIdx.y * 128;
    const int n0 = blockIdx.x * 128;

    const int a_row = tid >> 1;
    const int a_col = (tid & 1) * 4;
    const int b_row = tid >> 5;
    const int b_col = (tid & 31) * 4;

    const int ty = tid >> 4;
    const int tx = tid & 15;

    float acc[8][8];
#pragma unroll
    for (int i = 0; i < 8; i++)
#pragma unroll
        for (int j = 0; j < 8; j++) acc[i][j] = 0.f;

    for (int k0 = 0; k0 < K; k0 += 8) {
        float av[4];
        const int gm = m0 + a_row;
#pragma unroll
        for (int i = 0; i < 4; i++) {
            int gk = k0 + a_col + i;
            av[i] = (gm < M && gk < K) ? A[(size_t)gm * K + gk] : 0.f;
        }
#pragma unroll
        for (int i = 0; i < 4; i++) As[a_col + i][a_row] = av[i];

        float bv[4];
        const int gk = k0 + b_row;
#pragma unroll
        for (int i = 0; i < 4; i++) {
            int gn = n0 + b_col + i;
            bv[i] = (gk < K && gn < Nc) ? B[(size_t)gk * Nc + gn] : 0.f;
        }
        *(float4*)&Bs[b_row][b_col] = make_float4(bv[0], bv[1], bv[2], bv[3]);

        __syncthreads();

#pragma unroll
        for (int kk = 0; kk < 8; kk++) {
            float4 a0 = *(const float4*)&As[kk][ty * 8];
            float4 a1 = *(const float4*)&As[kk][ty * 8 + 4];
            float4 b0 = *(const float4*)&Bs[kk][tx * 8];
            float4 b1 = *(const float4*)&Bs[kk][tx * 8 + 4];
            float ar[8] = {a0.x, a0.y, a0.z, a0.w, a1.x, a1.y, a1.z, a1.w};
            float br[8] = {b0.x, b0.y, b0.z, b0.w, b1.x, b1.y, b1.z, b1.w};
#pragma unroll
            for (int i = 0; i < 8; i++)
#pragma unroll
                for (int j = 0; j < 8; j++)
                    acc[i][j] = fmaf(ar[i], br[j], acc[i][j]);
        }
        __syncthreads();
    }

#pragma unroll
    for (int i = 0; i < 8; i++) {
        int gm = m0 + ty * 8 + i;
        if (gm >= M) continue;
#pragma unroll
        for (int j = 0; j < 8; j++) {
            int gn = n0 + tx * 8 + j;
            if (gn >= Nc) continue;
            float v = acc[i][j];
            if (BIAS) v += bias[gn];
            if (RELU) v = v > 0.f ? v : 0.f;
            C[(size_t)gm * Nc + gn] = v;
        }
    }
}

// ============================================================
// Attention coefficients: a_src[n,h], a_dst[n,h] (warp per (n,h))
// ============================================================
__global__ void att_kernel(const float* __restrict__ h,
                           const float* __restrict__ att_s,
                           const float* __restrict__ att_d,
                           float* __restrict__ asrc, float* __restrict__ adst)
{
    int w = (blockIdx.x * blockDim.x + threadIdx.x) >> 5;
    if (w >= NN * HH) return;
    int lane = threadIdx.x & 31;
    int n = w / HH, hh = w % HH;
    const float* hp = h + (size_t)n * HIDC + hh * FF;
    const float* as = att_s + hh * FF;
    const float* ad = att_d + hh * FF;
    float s1 = 0.f, s2 = 0.f;
    for (int f = lane; f < FF; f += 32) {
        float v = hp[f];
        s1 += v * as[f];
        s2 += v * ad[f];
    }
#pragma unroll
    for (int o = 16; o; o >>= 1) {
        s1 += __shfl_down_sync(0xffffffffu, s1, o);
        s2 += __shfl_down_sync(0xffffffffu, s2, o);
    }
    if (!lane) { asrc[w] = s1; adst[w] = s2; }
}

// ============================================================
// Graph structure kernels
// ============================================================
__global__ void zero_int(int* p, int n)
{
    int i = blockIdx.x * blockDim.x + threadIdx.x;
    if (i < n) p[i] = 0;
}

__global__ void copy_int(const int* __restrict__ a, int* __restrict__ b, int n)
{
    int i = blockIdx.x * blockDim.x + threadIdx.x;
    if (i < n) b[i] = a[i];
}

__global__ void hist_deg(const int* __restrict__ ei, int* __restrict__ deg)
{
    int e = blockIdx.x * blockDim.x + threadIdx.x;
    if (e >= ET) return;
    int d = (e < EE) ? ei[EE + e] : (e - EE);
    atomicAdd(&deg[d], 1);
}

__global__ void hist_batch(const int* __restrict__ batch, int* __restrict__ cnt)
{
    int i = blockIdx.x * blockDim.x + threadIdx.x;
    if (i < NN) atomicAdd(&cnt[batch[i]], 1);
}

// single-block exclusive scan, out has n+1 entries (out[n] = total)
__global__ void scan_excl(const int* __restrict__ in, int* __restrict__ out, int n)
{
    __shared__ int sh[1024];
    __shared__ int carry;
    if (threadIdx.x == 0) carry = 0;
    __syncthreads();
    for (int base = 0; base < n; base += 1024) {
        int i = base + threadIdx.x;
        int v = (i < n) ? in[i] : 0;
        sh[threadIdx.x] = v;
        __syncthreads();
        for (int off = 1; off < 1024; off <<= 1) {
            int t = (threadIdx.x >= off) ? sh[threadIdx.x - off] : 0;
            __syncthreads();
            sh[threadIdx.x] += t;
            __syncthreads();
        }
        int c0 = carry;
        if (i < n) out[i] = c0 + sh[threadIdx.x] - v;
        __syncthreads();
        if (threadIdx.x == 0) carry = c0 + sh[1023];
        __syncthreads();
    }
    if (threadIdx.x == 0) out[n] = carry;
}

__global__ void scatter_csr(const int* __restrict__ ei, int* __restrict__ wptr,
                            int* __restrict__ csrc)
{
    int e = blockIdx.x * blockDim.x + threadIdx.x;
    if (e >= ET) return;
    int s = (e < EE) ? ei[e] : (e - EE);
    int d = (e < EE) ? ei[EE + e] : (e - EE);
    int pos = atomicAdd(&wptr[d], 1);
    csrc[pos] = s;
}

__global__ void dinv_kernel(const int* __restrict__ deg, float* __restrict__ dinv)
{
    int i = blockIdx.x * blockDim.x + threadIdx.x;
    if (i < NN) dinv[i] = rsqrtf(fmaxf((float)deg[i], 1.f));
}

// ============================================================
// GAT softmax-aggregate: warp per destination node. float4 path.
// ============================================================
__global__ __launch_bounds__(256)
void gat_agg(const float* __restrict__ h, const float* __restrict__ asrc,
             const float* __restrict__ adst, const int* __restrict__ rowptr,
             const int* __restrict__ csrc, const float* __restrict__ bgat,
             float* __restrict__ out1)
{
    __shared__ float wsh[8][HH];
    int warp = (blockIdx.x * 256 + threadIdx.x) >> 5;
    if (warp >= NN) return;
    int lane = threadIdx.x & 31;
    float* myw = wsh[(threadIdx.x >> 5)];
    int d = warp;
    int jb = rowptr[d], je = rowptr[d + 1];

    float ad = (lane < HH) ? adst[d * HH + lane] : 0.f;

    // pass 1: softmax denominator per head (lanes 0..9)
    float denom = 0.f;
    for (int j = jb; j < je; j++) {
        int s = csrc[j];
        if (lane < HH) {
            float ev = asrc[s * HH + lane] + ad;
            ev = ev > 0.f ? ev : 0.2f * ev;
            denom += __expf(ev);
        }
    }

    // per-component head indices for this lane's float4 slots
    int4 hd4[7];
#pragma unroll
    for (int k = 0; k < 7; k++) {
        int t = lane + k * 32;
        int e0 = 4 * ((t < H4) ? t : 0);
        hd4[k] = make_int4(e0 / FF, (e0 + 1) / FF, (e0 + 2) / FF, (e0 + 3) / FF);
    }

    float4 acc[7];
#pragma unroll
    for (int k = 0; k < 7; k++) acc[k] = make_float4(0.f, 0.f, 0.f, 0.f);

    // pass 2: weighted aggregate (float4 gathers)
    for (int j = jb; j < je; j++) {
        int s = csrc[j];
        if (lane < HH) {
            float ev = asrc[s * HH + lane] + ad;
            ev = ev > 0.f ? ev : 0.2f * ev;
            myw[lane] = __expf(ev) / denom;
        }
        __syncwarp();
        const float4* hp = (const float4*)(h + (size_t)s * HIDC);
#pragma unroll
        for (int k = 0; k < 7; k++) {
            int t = lane + k * 32;
            if (t < H4) {
                float4 v = hp[t];
                acc[k].x = fmaf(myw[hd4[k].x], v.x, acc[k].x);
                acc[k].y = fmaf(myw[hd4[k].y], v.y, acc[k].y);
                acc[k].z = fmaf(myw[hd4[k].z], v.z, acc[k].z);
                acc[k].w = fmaf(myw[hd4[k].w], v.w, acc[k].w);
            }
        }
        __syncwarp();
    }

    float4* op = (float4*)(out1 + (size_t)d * HIDC);
    const float4* bp = (const float4*)bgat;
#pragma unroll
    for (int k = 0; k < 7; k++) {
        int t = lane + k * 32;
        if (t < H4) {
            float4 b = bp[t];
            float4 v;
            v.x = fmaxf(acc[k].x + b.x, 0.f);
            v.y = fmaxf(acc[k].y + b.y, 0.f);
            v.z = fmaxf(acc[k].z + b.z, 0.f);
            v.w = fmaxf(acc[k].w + b.w, 0.f);
            op[t] = v;
        }
    }
}

// ============================================================
// GCN normalized aggregate: warp per destination node. float4.
// ============================================================
__global__ __launch_bounds__(256)
void gcn_agg(const float* __restrict__ h2, const float* __restrict__ dinv,
             const int* __restrict__ rowptr, const int* __restrict__ csrc,
             const float* __restrict__ bgcn, float* __restrict__ out2)
{
    int warp = (blockIdx.x * 256 + threadIdx.x) >> 5;
    if (warp >= NN) return;
    int lane = threadIdx.x & 31;
    int d = warp;
    int jb = rowptr[d], je = rowptr[d + 1];
    float dd = dinv[d];

    float4 acc[7];
#pragma unroll
    for (int k = 0; k < 7; k++) acc[k] = make_float4(0.f, 0.f, 0.f, 0.f);

    for (int j = jb; j < je; j++) {
        int s = csrc[j];
        float w = dinv[s] * dd;
        const float4* hp = (const float4*)(h2 + (size_t)s * HIDC);
#pragma unroll
        for (int k = 0; k < 7; k++) {
            int t = lane + k * 32;
            if (t < H4) {
                float4 v = hp[t];
                acc[k].x = fmaf(w, v.x, acc[k].x);
                acc[k].y = fmaf(w, v.y, acc[k].y);
                acc[k].z = fmaf(w, v.z, acc[k].z);
                acc[k].w = fmaf(w, v.w, acc[k].w);
            }
        }
    }

    float4* op = (float4*)(out2 + (size_t)d * HIDC);
    const float4* bp = (const float4*)bgcn;
#pragma unroll
    for (int k = 0; k < 7; k++) {
        int t = lane + k * 32;
        if (t < H4) {
            float4 b = bp[t];
            float4 v;
            v.x = fmaxf(acc[k].x + b.x, 0.f);
            v.y = fmaxf(acc[k].y + b.y, 0.f);
            v.z = fmaxf(acc[k].z + b.z, 0.f);
            v.w = fmaxf(acc[k].w + b.w, 0.f);
            op[t] = v;
        }
    }
}

// ============================================================
// Global mean/max pool, block per graph (batch is sorted), float4
// ============================================================
__global__ __launch_bounds__(256)
void pool_kernel(const float* __restrict__ out2, const int* __restrict__ gstart,
                 float* __restrict__ pooled)
{
    int g = blockIdx.x;
    int t = threadIdx.x;          // one float4 slot per thread (195 < 256)
    int start = gstart[g];
    int cnt = gstart[g + 1] - start;

    if (t >= H4) return;

    float4 s = make_float4(0.f, 0.f, 0.f, 0.f);
    float4 mx = make_float4(-INFINITY, -INFINITY, -INFINITY, -INFINITY);

    for (int i = 0; i < cnt; i++) {
        const float4* p = (const float4*)(out2 + (size_t)(start + i) * HIDC);
        float4 v = p[t];
        s.x += v.x; s.y += v.y; s.z += v.z; s.w += v.w;
        mx.x = fmaxf(mx.x, v.x); mx.y = fmaxf(mx.y, v.y);
        mx.z = fmaxf(mx.z, v.z); mx.w = fmaxf(mx.w, v.w);
    }
    float inv = 1.f / fmaxf((float)cnt, 1.f);
    float4 mean = make_float4(s.x * inv, s.y * inv, s.z * inv, s.w * inv);
    if (cnt <= 0) mx = make_float4(0.f, 0.f, 0.f, 0.f);

    float4* pm = (float4*)(pooled + (size_t)g * PO);
    float4* px = (float4*)(pooled + (size_t)g * PO + HIDC);
    pm[t] = mean;
    px[t] = mx;
}

// ============================================================
// Launch
// ============================================================
extern "C" void kernel_launch(void* const* d_in, const int* in_sizes, int n_in,
                              void* d_out, int out_size)
{
    const float* x     = (const float*)d_in[0];
    const int*   ei    = (const int*)  d_in[1];
    const int*   batch = (const int*)  d_in[2];
    const float* Wgat  = (const float*)d_in[3];
    const float* att_s = (const float*)d_in[4];
    const float* att_d = (const float*)d_in[5];
    const float* bgat  = (const float*)d_in[6];
    const float* Wgcn  = (const float*)d_in[7];
    const float* bgcn  = (const float*)d_in[8];
    const float* W1    = (const float*)d_in[9];
    const float* b1    = (const float*)d_in[10];
    const float* W2    = (const float*)d_in[11];
    const float* b2    = (const float*)d_in[12];
    float* out = (float*)d_out;

    float* base = nullptr;
    cudaGetSymbolAddress((void**)&base, g_buf);

    float* ph     = base + OFF_H;
    float* pout1  = base + OFF_OUT1;
    float* ph2    = base + OFF_H2;
    float* pout2  = base + OFF_OUT2;
    float* pasrc  = base + OFF_ASRC;
    float* padst  = base + OFF_ADST;
    float* pdinv  = base + OFF_DINV;
    float* ppool  = base + OFF_POOL;
    float* pfc1   = base + OFF_FC1;
    int*   pdeg   = (int*)(base + OFF_DEG);
    int*   prowp  = (int*)(base + OFF_ROWP);
    int*   pwptr  = (int*)(base + OFF_WPTR);
    int*   pcsrc  = (int*)(base + OFF_CSRC);
    int*   pcnt   = (int*)(base + OFF_CNT);
    int*   pgst   = (int*)(base + OFF_GST);

    // 1. h = x @ W_gat   [N, 780]  (fp32: feeds attention softmax)
    {
        dim3 grid((HIDC + 127) / 128, (NN + 127) / 128);
        sgemm<false, false><<<grid, 256>>>(x, Wgat, nullptr, ph, NN, FF, HIDC);
    }

    // 2. attention coefficients
    {
        int warps = NN * HH;
        int blocks = (warps * 32 + 255) / 256;
        att_kernel<<<blocks, 256>>>(ph, att_s, att_d, pasrc, padst);
    }

    // 3. CSR build + dinv
    zero_int<<<(NN + 255) / 256, 256>>>(pdeg, NN);
    hist_deg<<<(ET + 255) / 256, 256>>>(ei, pdeg);
    scan_excl<<<1, 1024>>>(pdeg, prowp, NN);
    copy_int<<<(NN + 255) / 256, 256>>>(prowp, pwptr, NN);
    scatter_csr<<<(ET + 255) / 256, 256>>>(ei, pwptr, pcsrc);
    dinv_kernel<<<(NN + 255) / 256, 256>>>(pdeg, pdinv);

    // 4. GAT softmax-aggregate + bias + relu
    gat_agg<<<(NN * 32 + 255) / 256, 256>>>(ph, pasrc, padst, prowp, pcsrc, bgat, pout1);

    // 5. h2 = out1 @ W_gcn   [N, 780]  (pipelined TF32 — dominant GEMM)
    {
        dim3 grid((HIDC + 127) / 128, (NN + 127) / 128);
        tf32_gemm_pipe<false, false><<<grid, 256>>>(pout1, Wgcn, nullptr, ph2, NN, HIDC, HIDC);
    }

    // 6. GCN aggregate + bias + relu
    gcn_agg<<<(NN * 32 + 255) / 256, 256>>>(ph2, pdinv, prowp, pcsrc, bgcn, pout2);

    // 7. graph node ranges (batch is sorted)
    zero_int<<<(GG + 255) / 256, 256>>>(pcnt, GG);
    hist_batch<<<(NN + 255) / 256, 256>>>(batch, pcnt);
    scan_excl<<<1, 1024>>>(pcnt, pgst, GG);

    // 8. mean/max pooling
    pool_kernel<<<GG, 256>>>(pout2, pgst, ppool);

    // 9. fc1 = relu(pooled @ W1 + b1)   (pipelined TF32)
    {
        dim3 grid((P1 + 127) / 128, (GG + 127) / 128);
        tf32_gemm_pipe<true, true><<<grid, 256>>>(ppool, W1, b1, pfc1, GG, PO, P1);
    }

    // 10. out = fc1 @ W2 + b2  (fp32: final layer, small)
    {
        dim3 grid((OC + 127) / 128, (GG + 127) / 128);
        sgemm<true, false><<<grid, 256>>>(pfc1, W2, b2, out, GG, P1, OC);
    }
}